// round 12
// baseline (speedup 1.0000x reference)
#include <cuda_runtime.h>
#include <cuda_fp16.h>
#include <math.h>

#define N_NODES 50000
#define DEG     16
#define WIDTH   256
#define BATCH   8192
#define EPS     1e-12f

#define LDB  264    // B staging leading dim (halves): 528B rows, conflict-free
#define LDH  264    // A/H1/nm2 smem leading dim (halves)

// ---- device globals: ~0.85MB total ----
__device__ int      g_owner[N_NODES];          // 200KB
__device__ __half   g_Wh[327680];              // 640KB: W0top|W0bot|W1|Wagg (fp16)
__device__ unsigned g_barCount;
__device__ unsigned g_barPhase;

// ---------------------------------------------------------------------------
// mma helpers
// ---------------------------------------------------------------------------
__device__ __forceinline__ unsigned smem_u32(const void* p) {
    return (unsigned)__cvta_generic_to_shared(p);
}
__device__ __forceinline__ void ldm_x4(unsigned& r0, unsigned& r1, unsigned& r2,
                                       unsigned& r3, unsigned a) {
    asm volatile("ldmatrix.sync.aligned.m8n8.x4.shared.b16 {%0,%1,%2,%3},[%4];"
                 : "=r"(r0), "=r"(r1), "=r"(r2), "=r"(r3) : "r"(a));
}
__device__ __forceinline__ void ldm_x4t(unsigned& r0, unsigned& r1, unsigned& r2,
                                        unsigned& r3, unsigned a) {
    asm volatile("ldmatrix.sync.aligned.m8n8.x4.trans.shared.b16 {%0,%1,%2,%3},[%4];"
                 : "=r"(r0), "=r"(r1), "=r"(r2), "=r"(r3) : "r"(a));
}
__device__ __forceinline__ void mma16816(float* c, unsigned a0, unsigned a1,
                                         unsigned a2, unsigned a3,
                                         unsigned b0, unsigned b1) {
    asm volatile(
        "mma.sync.aligned.m16n8k16.row.col.f32.f16.f16.f32 "
        "{%0,%1,%2,%3},{%4,%5,%6,%7},{%8,%9},{%0,%1,%2,%3};"
        : "+f"(c[0]), "+f"(c[1]), "+f"(c[2]), "+f"(c[3])
        : "r"(a0), "r"(a1), "r"(a2), "r"(a3), "r"(b0), "r"(b1));
}

struct LaneGeom { int aRow, aCol, bRow, bCol; };

__device__ __forceinline__ void mma_chunk(float (*c)[4], unsigned aBase, int lda,
                                          unsigned bBase, int n0, const LaneGeom& lg) {
#pragma unroll
    for (int ks = 0; ks < 2; ++ks) {
        const int k0 = ks * 16;
        unsigned a0, a1, a2, a3;
        ldm_x4(a0, a1, a2, a3,
               aBase + (unsigned)((lg.aRow * lda + k0 + lg.aCol) * 2));
#pragma unroll
        for (int jj = 0; jj < 4; ++jj) {
            unsigned b0, b1, b2, b3;
            ldm_x4t(b0, b1, b2, b3,
                    bBase + (unsigned)(((k0 + lg.bRow) * LDB + n0 + jj * 16 + lg.bCol) * 2));
            mma16816(c[2 * jj],     a0, a1, a2, a3, b0, b1);
            mma16816(c[2 * jj + 1], a0, a1, a2, a3, b2, b3);
        }
    }
}

// async-copy one 32-row fp16 W chunk (16KB) into a B buffer
__device__ __forceinline__ void issue_B(const __half* Wh, int kbase, __half* buf, int tid) {
#pragma unroll
    for (int p = 0; p < 2; ++p) {
        int o = tid + p * 512;
        int kk = o >> 5, seg = o & 31;
        unsigned dst = smem_u32(buf + kk * LDB + seg * 8);
        unsigned long long src =
            (unsigned long long)__cvta_generic_to_global(Wh + (kbase + kk) * 256 + seg * 8);
        asm volatile("cp.async.cg.shared.global [%0],[%1],16;" :: "r"(dst), "l"(src));
    }
    asm volatile("cp.async.commit_group;" ::: "memory");
}

// triple-buffered, ONE-sync-per-chunk pipelined GEMM over nChunks 32-K chunks.
// Chunk i lives in buf[i%3]. pre = number of chunks the caller already issued
// (chunk i -> buf[i%3]). NO trailing sync: callers must __syncthreads() before
// reusing the A tile or B buffers.
__device__ __forceinline__ void gemm_pipe(float (*c)[4], unsigned aLo, unsigned aHi,
                                          int lda, const __half* Wh, int nChunks,
                                          __half* B0, __half* B1, __half* B2,
                                          int tid, int n0, const LaneGeom& lg, int pre) {
    __half* bufs[3] = {B0, B1, B2};
    for (int i = pre; i < 2 && i < nChunks; ++i) issue_B(Wh, i * 32, bufs[i], tid);
#pragma unroll 1
    for (int t = 0; t < nChunks; ++t) {
        if (t < nChunks - 1)
            asm volatile("cp.async.wait_group 1;" ::: "memory");
        else
            asm volatile("cp.async.wait_group 0;" ::: "memory");
        __syncthreads();
        if (t + 2 < nChunks) issue_B(Wh, (t + 2) * 32, bufs[(t + 2) % 3], tid);
        unsigned aB = (t < 8) ? (aLo + (unsigned)(t * 64))
                              : (aHi + (unsigned)((t - 8) * 64));
        mma_chunk(c, aB, lda, smem_u32(bufs[t % 3]), n0, lg);
    }
}

// ---------------------------------------------------------------------------
// setup kernels
// ---------------------------------------------------------------------------
__global__ void init_owner_kernel() {
    int i = blockIdx.x * 256 + threadIdx.x;
    if (i < N_NODES) g_owner[i] = -1;
}
__global__ void owner_scatter_kernel(const int* __restrict__ node_idx) {
    int i = blockIdx.x * 256 + threadIdx.x;
    if (i < BATCH) atomicMax(&g_owner[node_idx[i]], i);   // last-wins on dups
}
// g_Wh = [W0top (256x256) | W0bot (256x256) | W1 (512x256) | Wagg (256x256)]
__global__ void convert_w_kernel(const float* __restrict__ W_agg,
                                 const float* __restrict__ W_lin) {
    int i = blockIdx.x * 256 + threadIdx.x;   // half2 index
    if (i < 131072) {
        float2 v = ((const float2*)W_lin)[i];
        ((__half2*)g_Wh)[i] = __floats2half2_rn(v.x, v.y);
    } else if (i < 163840) {
        float2 v = ((const float2*)W_agg)[i - 131072];
        ((__half2*)g_Wh)[i] = __floats2half2_rn(v.x, v.y);
    }
}

// ---------------------------------------------------------------------------
// merged pre GEMM (K=256): stage feats tile once, then
//   aggb = relu(feats @ Wagg + b_agg)   (fp16)
//   fW0  = feats @ W0top                (fp16)
// ---------------------------------------------------------------------------
#define PRE_SMEM (64*LDH*2 + 3*32*LDB*2 + 256*4)   // 85504

__global__ __launch_bounds__(512, 1)
void pre_gemm_kernel(const float* __restrict__ A, const float* __restrict__ bias_agg,
                     __half* __restrict__ aggb, __half* __restrict__ fW0) {
    extern __shared__ char smp[];
    __half* Af  = (__half*)smp;            // [64][264]
    __half* B0  = Af + 64 * LDH;
    __half* B1  = B0 + 32 * LDB;
    __half* B2  = B1 + 32 * LDB;
    float*  s_b = (float*)(B2 + 32 * LDB);

    const int tx = threadIdx.x, wid = threadIdx.y;
    const int tid = wid * 32 + tx;
    const int rowBase = blockIdx.x * 64;
    const int warpM = wid & 3, warpN = wid >> 2;
    const int row0 = warpM * 16, n0 = warpN * 64;
    const int g = tx >> 2, t4 = tx & 3, q = tx >> 3, rl = tx & 7;
    LaneGeom lg = {row0 + (q & 1) * 8 + rl, (q >> 1) * 8, (q & 1) * 8 + rl, (q >> 1) * 8};
    const int lr = tid >> 3, lk4 = tid & 7;

    if (tid < 256) s_b[tid] = __ldg(&bias_agg[tid]);
    // pre-issue Wagg chunks 0,1 to overlap with A staging
    issue_B(g_Wh + 262144, 0, B0, tid);
    issue_B(g_Wh + 262144, 32, B1, tid);

#pragma unroll
    for (int t = 0; t < 8; ++t) {
        float4 v = *(const float4*)&A[(rowBase + lr) * 256 + t * 32 + lk4 * 4];
        __half2* ad = (__half2*)&Af[lr * LDH + t * 32 + lk4 * 4];
        ad[0] = __floats2half2_rn(v.x, v.y);
        ad[1] = __floats2half2_rn(v.z, v.w);
    }

    const unsigned AfA = smem_u32(Af);
    const int rA = rowBase + row0 + g, rB = rA + 8;

    // ---- GEMM 1: aggb = relu(feats @ Wagg + b_agg) ----
    float c[8][4];
#pragma unroll
    for (int j = 0; j < 8; ++j)
#pragma unroll
        for (int k = 0; k < 4; ++k) c[j][k] = 0.f;
    gemm_pipe(c, AfA, AfA + 512, LDH, g_Wh + 262144, 8, B0, B1, B2, tid, n0, lg, 2);
#pragma unroll
    for (int j = 0; j < 8; ++j) {
        int n = n0 + j * 8 + 2 * t4;
        float b0v = s_b[n], b1v = s_b[n + 1];
        *(__half2*)&aggb[rA * 256 + n] =
            __floats2half2_rn(fmaxf(c[j][0] + b0v, 0.f), fmaxf(c[j][1] + b1v, 0.f));
        *(__half2*)&aggb[rB * 256 + n] =
            __floats2half2_rn(fmaxf(c[j][2] + b0v, 0.f), fmaxf(c[j][3] + b1v, 0.f));
    }
    __syncthreads();   // drain B-buffer readers before GEMM 2 reissues

    // ---- GEMM 2: fW0 = feats @ W0top ----
#pragma unroll
    for (int j = 0; j < 8; ++j)
#pragma unroll
        for (int k = 0; k < 4; ++k) c[j][k] = 0.f;
    gemm_pipe(c, AfA, AfA + 512, LDH, g_Wh, 8, B0, B1, B2, tid, n0, lg, 0);
#pragma unroll
    for (int j = 0; j < 8; ++j) {
        int n = n0 + j * 8 + 2 * t4;
        *(__half2*)&fW0[rA * 256 + n] = __floats2half2_rn(c[j][0], c[j][1]);
        *(__half2*)&fW0[rB * 256 + n] = __floats2half2_rn(c[j][2], c[j][3]);
    }
}

// ---------------------------------------------------------------------------
// H1 tile builder (K=256): COMPACTED owned-neighbor gather (avg 2.4 of 16
// neighbors are owned; unowned contribute one constant row relu(b_agg));
// accumulator initialized from fW0[owner]; GEMM vs W0bot; bias+relu+normalize.
// list[r*16..]: owned owner-ids; s_cnt[r]: count; s_un[r]: any-unowned flag.
// Assumes ssum[]==0 on entry; leaves 0.
// ---------------------------------------------------------------------------
__device__ __forceinline__ void compute_h1_tile(
    const __half* __restrict__ aggb, const __half* __restrict__ fW0,
    const int* __restrict__ oArr, const int* __restrict__ list,
    const int* __restrict__ s_cnt, const int* __restrict__ s_un,
    const __half* __restrict__ s_rbh, const float* __restrict__ s_bl0,
    float* __restrict__ ssum, __half* __restrict__ dstH1,
    __half* __restrict__ Anm1, __half* __restrict__ B0, __half* __restrict__ B1,
    __half* __restrict__ B2, const __half* __restrict__ W0both,
    int tid, int n0, const LaneGeom& lg, int lrA, int lrB2, int t4) {

    const int lr = tid >> 3, lk4 = tid & 7;
    // pre-issue W chunks 0,1: in flight during the gather below
    issue_B(W0both, 0, B0, tid);
    issue_B(W0both, 32, B1, tid);

    // nm1 gather: only owned neighbors; constant row once if any unowned
    const int* lst = &list[lr * DEG];
    const int k = s_cnt[lr];
    const int un = s_un[lr];
#pragma unroll 1
    for (int t = 0; t < 4; ++t) {
        const int colh = t * 64 + lk4 * 8;
        __half2 m0, m1, m2, m3;
        int d0;
        if (un) {
            uint4 rbv = *(const uint4*)&s_rbh[colh];
            m0 = *(__half2*)&rbv.x; m1 = *(__half2*)&rbv.y;
            m2 = *(__half2*)&rbv.z; m3 = *(__half2*)&rbv.w;
            d0 = 0;
        } else {
            uint4 w = __ldg((const uint4*)&aggb[lst[0] * 256 + colh]);
            m0 = *(__half2*)&w.x; m1 = *(__half2*)&w.y;
            m2 = *(__half2*)&w.z; m3 = *(__half2*)&w.w;
            d0 = 1;
        }
#pragma unroll 1
        for (int d = d0; d < k; ++d) {
            uint4 w = __ldg((const uint4*)&aggb[lst[d] * 256 + colh]);
            m0 = __hmax2(m0, *(__half2*)&w.x);
            m1 = __hmax2(m1, *(__half2*)&w.y);
            m2 = __hmax2(m2, *(__half2*)&w.z);
            m3 = __hmax2(m3, *(__half2*)&w.w);
        }
        uint4 mv;
        mv.x = *(unsigned*)&m0; mv.y = *(unsigned*)&m1;
        mv.z = *(unsigned*)&m2; mv.w = *(unsigned*)&m3;
        *(uint4*)&Anm1[lr * LDH + colh] = mv;
    }

    // init accumulator from fW0[owner] (H0 @ W0top contribution)
    float c[8][4];
    {
        const int oA = oArr[lrA], oB = oArr[lrB2];
#pragma unroll
        for (int j = 0; j < 8; ++j) {
            int n = n0 + j * 8 + 2 * t4;
            if (oA >= 0) {
                __half2 v = __ldg((const __half2*)&fW0[oA * 256 + n]);
                c[j][0] = __half2float(v.x); c[j][1] = __half2float(v.y);
            } else { c[j][0] = 0.f; c[j][1] = 0.f; }
            if (oB >= 0) {
                __half2 v = __ldg((const __half2*)&fW0[oB * 256 + n]);
                c[j][2] = __half2float(v.x); c[j][3] = __half2float(v.y);
            } else { c[j][2] = 0.f; c[j][3] = 0.f; }
        }
    }

    unsigned AnA = smem_u32(Anm1);
    gemm_pipe(c, AnA, AnA + 512, LDH, W0both, 8, B0, B1, B2, tid, n0, lg, 2);

    // epilogue: bias+relu, cross-warpN row-norm, write fp16 (dstH1 may alias Anm1)
    float ssA = 0.f, ssB = 0.f;
#pragma unroll
    for (int j = 0; j < 8; ++j) {
        int n = n0 + j * 8 + 2 * t4;
        float b0v = s_bl0[n], b1v = s_bl0[n + 1];
        c[j][0] = fmaxf(c[j][0] + b0v, 0.f);
        c[j][1] = fmaxf(c[j][1] + b1v, 0.f);
        c[j][2] = fmaxf(c[j][2] + b0v, 0.f);
        c[j][3] = fmaxf(c[j][3] + b1v, 0.f);
        ssA = fmaf(c[j][0], c[j][0], fmaf(c[j][1], c[j][1], ssA));
        ssB = fmaf(c[j][2], c[j][2], fmaf(c[j][3], c[j][3], ssB));
    }
    ssA += __shfl_xor_sync(0xffffffffu, ssA, 1);
    ssA += __shfl_xor_sync(0xffffffffu, ssA, 2);
    ssB += __shfl_xor_sync(0xffffffffu, ssB, 1);
    ssB += __shfl_xor_sync(0xffffffffu, ssB, 2);
    if (t4 == 0) { atomicAdd(&ssum[lrA], ssA); atomicAdd(&ssum[lrB2], ssB); }
    __syncthreads();   // also drains all mma readers of Anm1 / B bufs
    float invA = 1.f / fmaxf(sqrtf(ssum[lrA]), EPS);
    float invB = 1.f / fmaxf(sqrtf(ssum[lrB2]), EPS);
    __syncthreads();
    if (tid < 64) ssum[tid] = 0.f;
#pragma unroll
    for (int j = 0; j < 8; ++j) {
        int n = n0 + j * 8 + 2 * t4;
        *(__half2*)&dstH1[lrA * LDH + n]  =
            __floats2half2_rn(c[j][0] * invA, c[j][1] * invA);
        *(__half2*)&dstH1[lrB2 * LDH + n] =
            __floats2half2_rn(c[j][2] * invB, c[j][3] * invB);
    }
    __syncthreads();
}

// ---------------------------------------------------------------------------
// final2: one block per 64 batch rows; fully local recompute (K=256 H1 tiles).
// ---------------------------------------------------------------------------
#define F2_SMEM (3*64*LDH*2 + 3*32*LDB*2 + (256*3+64)*4 + 256*2 + (4*64 + 64*DEG + 2*64)*4)

__global__ __launch_bounds__(512, 1)
void final2_kernel(const int* __restrict__ node_idx, const int* __restrict__ nbd,
                   const float* __restrict__ b_agg, const float* __restrict__ b0v_,
                   const float* __restrict__ b1v_,
                   const __half* __restrict__ aggb, const __half* __restrict__ fW0,
                   float* __restrict__ out) {
    extern __shared__ char smp[];
    __half* Anm1   = (__half*)smp;                 // [64][264]; reused as h1t
    __half* selfH1 = Anm1 + 64 * LDH;              // [64][264]
    __half* nm2    = selfH1 + 64 * LDH;            // [64][264]
    __half* B0     = nm2 + 64 * LDH;               // [32][264] x3
    __half* B1     = B0 + 32 * LDB;
    __half* B2     = B1 + 32 * LDB;
    float*  s_bagg = (float*)(B2 + 32 * LDB);      // 256
    float*  s_bl0  = s_bagg + 256;
    float*  s_bl1  = s_bl0 + 256;
    float*  ssum   = s_bl1 + 256;                  // 64
    __half* s_rbh  = (__half*)(ssum + 64);         // 256 halves: relu(b_agg) fp16
    int*    xs     = (int*)(s_rbh + 256);          // 64
    int*    oS     = xs + 64;                      // 64
    int*    oT     = oS + 64;                      // 64
    int*    s_nid  = oT + 64;                      // 64
    int*    list   = s_nid + 64;                   // [64][16] raw -> compacted
    int*    s_cnt  = list + 64 * DEG;              // 64
    int*    s_un   = s_cnt + 64;                   // 64

    const int tx = threadIdx.x, wid = threadIdx.y;
    const int tid = wid * 32 + tx;
    const int rB = blockIdx.x * 64;
    const int warpM = wid & 3, warpN = wid >> 2;
    const int row0 = warpM * 16, n0 = warpN * 64;
    const int g = tx >> 2, t4 = tx & 3, q = tx >> 3, rl = tx & 7;
    LaneGeom lg = {row0 + (q & 1) * 8 + rl, (q >> 1) * 8, (q & 1) * 8 + rl, (q >> 1) * 8};
    const int lrA = row0 + g, lrB2 = lrA + 8;

    const __half* W0both = g_Wh + 65536;
    const __half* W1h    = g_Wh + 131072;

    if (tid < 256) {
        float ba = __ldg(&b_agg[tid]);
        s_bagg[tid] = ba;
        s_rbh[tid]  = __float2half_rn(fmaxf(ba, 0.f));
        s_bl0[tid]  = __ldg(&b0v_[tid]);
        s_bl1[tid]  = __ldg(&b1v_[tid]);
    }
    if (tid < 64) {
        ssum[tid] = 0.f;
        int x = __ldg(&node_idx[rB + tid]);
        xs[tid] = x;
        oS[tid] = g_owner[x];
    }
    __syncthreads();
    // raw neighbor owner fill for SELF tile, then in-place compaction
    for (int e = tid; e < 64 * DEG; e += 512)
        list[e] = g_owner[__ldg(&nbd[xs[e >> 4] * DEG + (e & 15)])];
    __syncthreads();
    if (tid < 64) {
        int cnt = 0, un = 0;
#pragma unroll
        for (int d = 0; d < DEG; ++d) {
            int o = list[tid * DEG + d];
            if (o >= 0) list[tid * DEG + cnt++] = o;   // forward in-place: safe
            else un = 1;
        }
        s_cnt[tid] = cnt; s_un[tid] = un;
    }
    __syncthreads();

    const unsigned h1tA = smem_u32(Anm1);
    const unsigned selfA = smem_u32(selfH1), nm2A = smem_u32(nm2);

    // ---- self H1 tile ----
    compute_h1_tile(aggb, fW0, oS, list, s_cnt, s_un, s_rbh, s_bl0, ssum, selfH1,
                    Anm1, B0, B1, B2, W0both, tid, n0, lg, lrA, lrB2, t4);

    // ---- 16 neighbor tiles: H1 -> agg2 -> group-max into nm2 ----
#pragma unroll 1
    for (int nt = 0; nt < 16; ++nt) {
        if (tid < 64) {
            int il = nt * 4 + (tid >> 4);
            int n = __ldg(&nbd[xs[il] * DEG + (tid & 15)]);
            s_nid[tid] = n;
            oT[tid] = g_owner[n];
        }
        __syncthreads();
        for (int e = tid; e < 64 * DEG; e += 512)
            list[e] = g_owner[__ldg(&nbd[s_nid[e >> 4] * DEG + (e & 15)])];
        __syncthreads();
        if (tid < 64) {
            int cnt = 0, un = 0;
#pragma unroll
            for (int d = 0; d < DEG; ++d) {
                int o = list[tid * DEG + d];
                if (o >= 0) list[tid * DEG + cnt++] = o;
                else un = 1;
            }
            s_cnt[tid] = cnt; s_un[tid] = un;
        }
        __syncthreads();

        // H1 of the 64 neighbor nodes -> h1t (reuses Anm1 region)
        compute_h1_tile(aggb, fW0, oT, list, s_cnt, s_un, s_rbh, s_bl0, ssum,
                        Anm1, Anm1, B0, B1, B2, W0both, tid, n0, lg, lrA, lrB2, t4);

        // agg2 = relu(h1t @ W_agg + b_agg)
        float c[8][4];
#pragma unroll
        for (int j = 0; j < 8; ++j)
#pragma unroll
            for (int k = 0; k < 4; ++k) c[j][k] = 0.f;
        gemm_pipe(c, h1tA, h1tA + 512, LDH, g_Wh + 262144, 8, B0, B1, B2,
                  tid, n0, lg, 0);

        // bias+relu, max over this warpM group's 16 rows (one batch entry)
#pragma unroll
        for (int j = 0; j < 8; ++j) {
            int n = n0 + j * 8 + 2 * t4;
            float bb0 = s_bagg[n], bb1 = s_bagg[n + 1];
            float a0 = fmaxf(fmaxf(c[j][0] + bb0, 0.f), fmaxf(c[j][2] + bb0, 0.f));
            float a1 = fmaxf(fmaxf(c[j][1] + bb1, 0.f), fmaxf(c[j][3] + bb1, 0.f));
#pragma unroll
            for (int mask = 4; mask <= 16; mask <<= 1) {
                a0 = fmaxf(a0, __shfl_xor_sync(0xffffffffu, a0, mask));
                a1 = fmaxf(a1, __shfl_xor_sync(0xffffffffu, a1, mask));
            }
            *(__half2*)&nm2[(nt * 4 + warpM) * LDH + n] = __floats2half2_rn(a0, a1);
        }
        __syncthreads();   // drains agg2 mma readers; protects B-buf reuse next tile
    }

    // ---- final GEMM: [selfH1 | nm2] @ W1, K=512 ----
    float c[8][4];
#pragma unroll
    for (int j = 0; j < 8; ++j)
#pragma unroll
        for (int k = 0; k < 4; ++k) c[j][k] = 0.f;
    gemm_pipe(c, selfA, nm2A, LDH, W1h, 16, B0, B1, B2, tid, n0, lg, 0);

    // epilogue: bias+relu+normalize (values stay in registers across barrier)
    float invA, invB;
    {
        float ssA = 0.f, ssB = 0.f;
#pragma unroll
        for (int j = 0; j < 8; ++j) {
            int n = n0 + j * 8 + 2 * t4;
            float bb0 = s_bl1[n], bb1 = s_bl1[n + 1];
            c[j][0] = fmaxf(c[j][0] + bb0, 0.f);
            c[j][1] = fmaxf(c[j][1] + bb1, 0.f);
            c[j][2] = fmaxf(c[j][2] + bb0, 0.f);
            c[j][3] = fmaxf(c[j][3] + bb1, 0.f);
            ssA = fmaf(c[j][0], c[j][0], fmaf(c[j][1], c[j][1], ssA));
            ssB = fmaf(c[j][2], c[j][2], fmaf(c[j][3], c[j][3], ssB));
        }
        ssA += __shfl_xor_sync(0xffffffffu, ssA, 1);
        ssA += __shfl_xor_sync(0xffffffffu, ssA, 2);
        ssB += __shfl_xor_sync(0xffffffffu, ssB, 1);
        ssB += __shfl_xor_sync(0xffffffffu, ssB, 2);
        if (t4 == 0) { atomicAdd(&ssum[lrA], ssA); atomicAdd(&ssum[lrB2], ssB); }
        __syncthreads();
        invA = 1.f / fmaxf(sqrtf(ssum[lrA]), EPS);
        invB = 1.f / fmaxf(sqrtf(ssum[lrB2]), EPS);
    }

    // ---- grid barrier: all d_out reads (aggb/fW0) done before overwrite ----
    __syncthreads();
    if (tid == 0) {
        unsigned phase = atomicAdd(&g_barPhase, 0u);
        unsigned t = atomicAdd(&g_barCount, 1u);
        if (t == gridDim.x - 1) {
            g_barCount = 0u;
            __threadfence();
            atomicAdd(&g_barPhase, 1u);
        } else {
            while (atomicAdd(&g_barPhase, 0u) == phase) { }
        }
    }
    __syncthreads();

    // ---- write out ----
#pragma unroll
    for (int j = 0; j < 8; ++j) {
        int n = n0 + j * 8 + 2 * t4;
        *(float2*)&out[(rB + lrA) * 256 + n] =
            make_float2(c[j][0] * invA, c[j][1] * invA);
        *(float2*)&out[(rB + lrB2) * 256 + n] =
            make_float2(c[j][2] * invB, c[j][3] * invB);
    }
}

// ---------------------------------------------------------------------------
// launch: node_idx, feats, nbd, W_agg, b_agg, W_lin, b_lin  -> out [B,256]
// ---------------------------------------------------------------------------
extern "C" void kernel_launch(void* const* d_in, const int* in_sizes, int n_in,
                              void* d_out, int out_size) {
    const int*   node_idx = (const int*)d_in[0];
    const float* feats    = (const float*)d_in[1];
    const int*   nbd      = (const int*)d_in[2];
    const float* W_agg    = (const float*)d_in[3];
    const float* b_agg    = (const float*)d_in[4];
    const float* W_lin    = (const float*)d_in[5];  // [2, 512, 256]
    const float* b_lin    = (const float*)d_in[6];  // [2, 256]

    // d_out: [0, 4.19MB) aggb fp16 | [4.19MB, 8.39MB) fW0 fp16 (exact fit)
    __half* aggb = (__half*)d_out;
    __half* fW0  = (__half*)d_out + BATCH * WIDTH;
    float*  out  = (float*)d_out;                  // overwritten post-barrier

    cudaFuncSetAttribute(pre_gemm_kernel,
                         cudaFuncAttributeMaxDynamicSharedMemorySize, PRE_SMEM);
    cudaFuncSetAttribute(final2_kernel,
                         cudaFuncAttributeMaxDynamicSharedMemorySize, F2_SMEM);

    dim3 gblk(32, 16);
    init_owner_kernel<<<(N_NODES + 255) / 256, 256>>>();
    owner_scatter_kernel<<<(BATCH + 255) / 256, 256>>>(node_idx);
    convert_w_kernel<<<640, 256>>>(W_agg, W_lin);
    pre_gemm_kernel<<<BATCH / 64, gblk, PRE_SMEM>>>(feats, b_agg, aggb, fW0);
    final2_kernel<<<BATCH / 64, gblk, F2_SMEM>>>(
        node_idx, nbd, b_agg, b_lin, b_lin + 256, aggb, fW0, out);
}

// round 13
// speedup vs baseline: 1.1872x; 1.1872x over previous
#include <cuda_runtime.h>
#include <cuda_fp16.h>
#include <math.h>

#define N_NODES 50000
#define DEG     16
#define WIDTH   256
#define BATCH   8192
#define EPS     1e-12f

#define LDB  264    // B staging leading dim (halves): 528B rows, conflict-free
#define LDH  264    // A/H1/nm2 smem leading dim (halves)

// ---- device globals: ~0.85MB total ----
__device__ int      g_owner[N_NODES];          // 200KB
__device__ __half   g_Wh[327680];              // 640KB: W0top|W0bot|W1|Wagg (fp16)
__device__ unsigned g_barCount;
__device__ unsigned g_barPhase;

// ---------------------------------------------------------------------------
// mma helpers
// ---------------------------------------------------------------------------
__device__ __forceinline__ unsigned smem_u32(const void* p) {
    return (unsigned)__cvta_generic_to_shared(p);
}
__device__ __forceinline__ void ldm_x4(unsigned& r0, unsigned& r1, unsigned& r2,
                                       unsigned& r3, unsigned a) {
    asm volatile("ldmatrix.sync.aligned.m8n8.x4.shared.b16 {%0,%1,%2,%3},[%4];"
                 : "=r"(r0), "=r"(r1), "=r"(r2), "=r"(r3) : "r"(a));
}
__device__ __forceinline__ void ldm_x4t(unsigned& r0, unsigned& r1, unsigned& r2,
                                        unsigned& r3, unsigned a) {
    asm volatile("ldmatrix.sync.aligned.m8n8.x4.trans.shared.b16 {%0,%1,%2,%3},[%4];"
                 : "=r"(r0), "=r"(r1), "=r"(r2), "=r"(r3) : "r"(a));
}
__device__ __forceinline__ void mma16816(float* c, unsigned a0, unsigned a1,
                                         unsigned a2, unsigned a3,
                                         unsigned b0, unsigned b1) {
    asm volatile(
        "mma.sync.aligned.m16n8k16.row.col.f32.f16.f16.f32 "
        "{%0,%1,%2,%3},{%4,%5,%6,%7},{%8,%9},{%0,%1,%2,%3};"
        : "+f"(c[0]), "+f"(c[1]), "+f"(c[2]), "+f"(c[3])
        : "r"(a0), "r"(a1), "r"(a2), "r"(a3), "r"(b0), "r"(b1));
}

struct LaneGeom { int aRow, aCol, bRow, bCol; };

__device__ __forceinline__ void mma_chunk(float (*c)[4], unsigned aBase, int lda,
                                          unsigned bBase, int n0, const LaneGeom& lg) {
#pragma unroll
    for (int ks = 0; ks < 2; ++ks) {
        const int k0 = ks * 16;
        unsigned a0, a1, a2, a3;
        ldm_x4(a0, a1, a2, a3,
               aBase + (unsigned)((lg.aRow * lda + k0 + lg.aCol) * 2));
#pragma unroll
        for (int jj = 0; jj < 4; ++jj) {
            unsigned b0, b1, b2, b3;
            ldm_x4t(b0, b1, b2, b3,
                    bBase + (unsigned)(((k0 + lg.bRow) * LDB + n0 + jj * 16 + lg.bCol) * 2));
            mma16816(c[2 * jj],     a0, a1, a2, a3, b0, b1);
            mma16816(c[2 * jj + 1], a0, a1, a2, a3, b2, b3);
        }
    }
}

// async-copy one 32-row fp16 W chunk (16KB) into a B buffer
__device__ __forceinline__ void issue_B(const __half* Wh, int kbase, __half* buf, int tid) {
#pragma unroll
    for (int p = 0; p < 2; ++p) {
        int o = tid + p * 512;
        int kk = o >> 5, seg = o & 31;
        unsigned dst = smem_u32(buf + kk * LDB + seg * 8);
        unsigned long long src =
            (unsigned long long)__cvta_generic_to_global(Wh + (kbase + kk) * 256 + seg * 8);
        asm volatile("cp.async.cg.shared.global [%0],[%1],16;" :: "r"(dst), "l"(src));
    }
    asm volatile("cp.async.commit_group;" ::: "memory");
}

// triple-buffered, ONE-sync-per-chunk pipelined GEMM over nChunks 32-K chunks.
// Chunk i lives in buf[i%3]. pre = number of chunks the caller already issued.
// NO trailing sync: callers must __syncthreads() before reusing A tile / B bufs
// (all call sites below do, via their epilogue or inter-GEMM syncs).
__device__ __forceinline__ void gemm_pipe(float (*c)[4], unsigned aLo, unsigned aHi,
                                          int lda, const __half* Wh, int nChunks,
                                          __half* B0, __half* B1, __half* B2,
                                          int tid, int n0, const LaneGeom& lg, int pre) {
    __half* bufs[3] = {B0, B1, B2};
    for (int i = pre; i < 2 && i < nChunks; ++i) issue_B(Wh, i * 32, bufs[i], tid);
#pragma unroll 1
    for (int t = 0; t < nChunks; ++t) {
        if (t < nChunks - 1)
            asm volatile("cp.async.wait_group 1;" ::: "memory");
        else
            asm volatile("cp.async.wait_group 0;" ::: "memory");
        __syncthreads();
        if (t + 2 < nChunks) issue_B(Wh, (t + 2) * 32, bufs[(t + 2) % 3], tid);
        unsigned aB = (t < 8) ? (aLo + (unsigned)(t * 64))
                              : (aHi + (unsigned)((t - 8) * 64));
        mma_chunk(c, aB, lda, smem_u32(bufs[t % 3]), n0, lg);
    }
}

// ---------------------------------------------------------------------------
// setup kernels
// ---------------------------------------------------------------------------
__global__ void init_owner_kernel() {
    int i = blockIdx.x * 256 + threadIdx.x;
    if (i < N_NODES) g_owner[i] = -1;
}
__global__ void owner_scatter_kernel(const int* __restrict__ node_idx) {
    int i = blockIdx.x * 256 + threadIdx.x;
    if (i < BATCH) atomicMax(&g_owner[node_idx[i]], i);   // last-wins on dups
}
// g_Wh = [W0top (256x256) | W0bot (256x256) | W1 (512x256) | Wagg (256x256)]
__global__ void convert_w_kernel(const float* __restrict__ W_agg,
                                 const float* __restrict__ W_lin) {
    int i = blockIdx.x * 256 + threadIdx.x;   // half2 index
    if (i < 131072) {
        float2 v = ((const float2*)W_lin)[i];
        ((__half2*)g_Wh)[i] = __floats2half2_rn(v.x, v.y);
    } else if (i < 163840) {
        float2 v = ((const float2*)W_agg)[i - 131072];
        ((__half2*)g_Wh)[i] = __floats2half2_rn(v.x, v.y);
    }
}

// ---------------------------------------------------------------------------
// merged pre GEMM (K=256): stage feats tile once, then
//   aggb = relu(feats @ Wagg + b_agg)   (fp16)
//   fW0  = feats @ W0top                (fp16)
// ---------------------------------------------------------------------------
#define PRE_SMEM (64*LDH*2 + 3*32*LDB*2 + 256*4)   // 85504

__global__ __launch_bounds__(512, 1)
void pre_gemm_kernel(const float* __restrict__ A, const float* __restrict__ bias_agg,
                     __half* __restrict__ aggb, __half* __restrict__ fW0) {
    extern __shared__ char smp[];
    __half* Af  = (__half*)smp;            // [64][264]
    __half* B0  = Af + 64 * LDH;
    __half* B1  = B0 + 32 * LDB;
    __half* B2  = B1 + 32 * LDB;
    float*  s_b = (float*)(B2 + 32 * LDB);

    const int tx = threadIdx.x, wid = threadIdx.y;
    const int tid = wid * 32 + tx;
    const int rowBase = blockIdx.x * 64;
    const int warpM = wid & 3, warpN = wid >> 2;
    const int row0 = warpM * 16, n0 = warpN * 64;
    const int g = tx >> 2, t4 = tx & 3, q = tx >> 3, rl = tx & 7;
    LaneGeom lg = {row0 + (q & 1) * 8 + rl, (q >> 1) * 8, (q & 1) * 8 + rl, (q >> 1) * 8};
    const int lr = tid >> 3, lk4 = tid & 7;

    if (tid < 256) s_b[tid] = __ldg(&bias_agg[tid]);
    // pre-issue Wagg chunks 0,1 to overlap with A staging
    issue_B(g_Wh + 262144, 0, B0, tid);
    issue_B(g_Wh + 262144, 32, B1, tid);

#pragma unroll
    for (int t = 0; t < 8; ++t) {
        float4 v = *(const float4*)&A[(rowBase + lr) * 256 + t * 32 + lk4 * 4];
        __half2* ad = (__half2*)&Af[lr * LDH + t * 32 + lk4 * 4];
        ad[0] = __floats2half2_rn(v.x, v.y);
        ad[1] = __floats2half2_rn(v.z, v.w);
    }

    const unsigned AfA = smem_u32(Af);
    const int rA = rowBase + row0 + g, rB = rA + 8;

    // ---- GEMM 1: aggb = relu(feats @ Wagg + b_agg) ----
    float c[8][4];
#pragma unroll
    for (int j = 0; j < 8; ++j)
#pragma unroll
        for (int k = 0; k < 4; ++k) c[j][k] = 0.f;
    gemm_pipe(c, AfA, AfA + 512, LDH, g_Wh + 262144, 8, B0, B1, B2, tid, n0, lg, 2);
#pragma unroll
    for (int j = 0; j < 8; ++j) {
        int n = n0 + j * 8 + 2 * t4;
        float b0v = s_b[n], b1v = s_b[n + 1];
        *(__half2*)&aggb[rA * 256 + n] =
            __floats2half2_rn(fmaxf(c[j][0] + b0v, 0.f), fmaxf(c[j][1] + b1v, 0.f));
        *(__half2*)&aggb[rB * 256 + n] =
            __floats2half2_rn(fmaxf(c[j][2] + b0v, 0.f), fmaxf(c[j][3] + b1v, 0.f));
    }
    __syncthreads();   // drain B-buffer readers before GEMM 2 reissues

    // ---- GEMM 2: fW0 = feats @ W0top ----
#pragma unroll
    for (int j = 0; j < 8; ++j)
#pragma unroll
        for (int k = 0; k < 4; ++k) c[j][k] = 0.f;
    gemm_pipe(c, AfA, AfA + 512, LDH, g_Wh, 8, B0, B1, B2, tid, n0, lg, 0);
#pragma unroll
    for (int j = 0; j < 8; ++j) {
        int n = n0 + j * 8 + 2 * t4;
        *(__half2*)&fW0[rA * 256 + n] = __floats2half2_rn(c[j][0], c[j][1]);
        *(__half2*)&fW0[rB * 256 + n] = __floats2half2_rn(c[j][2], c[j][3]);
    }
}

// ---------------------------------------------------------------------------
// H1 tile builder (K=256): vectorized fp16 nm1 gather — FULLY UNROLLED over
// DEG (16 independent 16B loads in flight per t-chunk; latency-hiding, the
// R12 compaction destroyed this and regressed). Accumulator initialized from
// fW0[owner]; GEMM vs W0bot; bias+relu+normalize. ssum[]==0 on entry/exit.
// ---------------------------------------------------------------------------
__device__ __forceinline__ void compute_h1_tile(
    const __half* __restrict__ aggb, const __half* __restrict__ fW0,
    const int* __restrict__ oArr, const int* __restrict__ nboArr,
    const __half* __restrict__ s_rbh, const float* __restrict__ s_bl0,
    float* __restrict__ ssum, __half* __restrict__ dstH1,
    __half* __restrict__ Anm1, __half* __restrict__ B0, __half* __restrict__ B1,
    __half* __restrict__ B2, const __half* __restrict__ W0both,
    int tid, int n0, const LaneGeom& lg, int lrA, int lrB2, int t4) {

    const int lr = tid >> 3, lk4 = tid & 7;
    // pre-issue W chunks 0,1: in flight during the gather below
    issue_B(W0both, 0, B0, tid);
    issue_B(W0both, 32, B1, tid);

    // nm1 gather: 16B loads, fp16 max, direct fp16 store into A tile
    const int* nbo = &nboArr[lr * DEG];
#pragma unroll 1
    for (int t = 0; t < 4; ++t) {
        const int colh = t * 64 + lk4 * 8;         // half offset within row
        uint4 rbv = *(const uint4*)&s_rbh[colh];
        int on0 = nbo[0];
        uint4 w0 = (on0 >= 0) ? __ldg((const uint4*)&aggb[on0 * 256 + colh]) : rbv;
        __half2 m0 = *(__half2*)&w0.x, m1 = *(__half2*)&w0.y;
        __half2 m2 = *(__half2*)&w0.z, m3 = *(__half2*)&w0.w;
#pragma unroll
        for (int d = 1; d < DEG; ++d) {
            int on = nbo[d];
            uint4 w = (on >= 0) ? __ldg((const uint4*)&aggb[on * 256 + colh]) : rbv;
            m0 = __hmax2(m0, *(__half2*)&w.x);
            m1 = __hmax2(m1, *(__half2*)&w.y);
            m2 = __hmax2(m2, *(__half2*)&w.z);
            m3 = __hmax2(m3, *(__half2*)&w.w);
        }
        uint4 mv;
        mv.x = *(unsigned*)&m0; mv.y = *(unsigned*)&m1;
        mv.z = *(unsigned*)&m2; mv.w = *(unsigned*)&m3;
        *(uint4*)&Anm1[lr * LDH + colh] = mv;
    }

    // init accumulator from fW0[owner] (H0 @ W0top contribution)
    float c[8][4];
    {
        const int oA = oArr[lrA], oB = oArr[lrB2];
#pragma unroll
        for (int j = 0; j < 8; ++j) {
            int n = n0 + j * 8 + 2 * t4;
            if (oA >= 0) {
                __half2 v = __ldg((const __half2*)&fW0[oA * 256 + n]);
                c[j][0] = __half2float(v.x); c[j][1] = __half2float(v.y);
            } else { c[j][0] = 0.f; c[j][1] = 0.f; }
            if (oB >= 0) {
                __half2 v = __ldg((const __half2*)&fW0[oB * 256 + n]);
                c[j][2] = __half2float(v.x); c[j][3] = __half2float(v.y);
            } else { c[j][2] = 0.f; c[j][3] = 0.f; }
        }
    }

    unsigned AnA = smem_u32(Anm1);
    gemm_pipe(c, AnA, AnA + 512, LDH, W0both, 8, B0, B1, B2, tid, n0, lg, 2);

    // epilogue: bias+relu, cross-warpN row-norm, write fp16 (dstH1 may alias Anm1)
    float ssA = 0.f, ssB = 0.f;
#pragma unroll
    for (int j = 0; j < 8; ++j) {
        int n = n0 + j * 8 + 2 * t4;
        float b0v = s_bl0[n], b1v = s_bl0[n + 1];
        c[j][0] = fmaxf(c[j][0] + b0v, 0.f);
        c[j][1] = fmaxf(c[j][1] + b1v, 0.f);
        c[j][2] = fmaxf(c[j][2] + b0v, 0.f);
        c[j][3] = fmaxf(c[j][3] + b1v, 0.f);
        ssA = fmaf(c[j][0], c[j][0], fmaf(c[j][1], c[j][1], ssA));
        ssB = fmaf(c[j][2], c[j][2], fmaf(c[j][3], c[j][3], ssB));
    }
    ssA += __shfl_xor_sync(0xffffffffu, ssA, 1);
    ssA += __shfl_xor_sync(0xffffffffu, ssA, 2);
    ssB += __shfl_xor_sync(0xffffffffu, ssB, 1);
    ssB += __shfl_xor_sync(0xffffffffu, ssB, 2);
    if (t4 == 0) { atomicAdd(&ssum[lrA], ssA); atomicAdd(&ssum[lrB2], ssB); }
    __syncthreads();   // drains all mma readers of Anm1 / B bufs too
    float invA = 1.f / fmaxf(sqrtf(ssum[lrA]), EPS);
    float invB = 1.f / fmaxf(sqrtf(ssum[lrB2]), EPS);
    __syncthreads();
    if (tid < 64) ssum[tid] = 0.f;
#pragma unroll
    for (int j = 0; j < 8; ++j) {
        int n = n0 + j * 8 + 2 * t4;
        *(__half2*)&dstH1[lrA * LDH + n]  =
            __floats2half2_rn(c[j][0] * invA, c[j][1] * invA);
        *(__half2*)&dstH1[lrB2 * LDH + n] =
            __floats2half2_rn(c[j][2] * invB, c[j][3] * invB);
    }
    __syncthreads();
}

// ---------------------------------------------------------------------------
// final2: one block per 64 batch rows; fully local recompute (K=256 H1 tiles).
// ---------------------------------------------------------------------------
#define F2_SMEM (3*64*LDH*2 + 3*32*LDB*2 + (256*3+64)*4 + 256*2 + (4*64 + 2*64*DEG)*4)

__global__ __launch_bounds__(512, 1)
void final2_kernel(const int* __restrict__ node_idx, const int* __restrict__ nbd,
                   const float* __restrict__ b_agg, const float* __restrict__ b0v_,
                   const float* __restrict__ b1v_,
                   const __half* __restrict__ aggb, const __half* __restrict__ fW0,
                   float* __restrict__ out) {
    extern __shared__ char smp[];
    __half* Anm1   = (__half*)smp;                 // [64][264]; reused as h1t
    __half* selfH1 = Anm1 + 64 * LDH;              // [64][264]
    __half* nm2    = selfH1 + 64 * LDH;            // [64][264]
    __half* B0     = nm2 + 64 * LDH;               // [32][264] x3
    __half* B1     = B0 + 32 * LDB;
    __half* B2     = B1 + 32 * LDB;
    float*  s_bagg = (float*)(B2 + 32 * LDB);      // 256
    float*  s_bl0  = s_bagg + 256;
    float*  s_bl1  = s_bl0 + 256;
    float*  ssum   = s_bl1 + 256;                  // 64
    __half* s_rbh  = (__half*)(ssum + 64);         // 256 halves: relu(b_agg) fp16
    int*    xs     = (int*)(s_rbh + 256);          // 64
    int*    oS     = xs + 64;
    int*    oT     = oS + 64;
    int*    s_nid  = oT + 64;
    int*    nboS   = s_nid + 64;                   // 1024
    int*    nboT   = nboS + 1024;                  // 1024

    const int tx = threadIdx.x, wid = threadIdx.y;
    const int tid = wid * 32 + tx;
    const int rB = blockIdx.x * 64;
    const int warpM = wid & 3, warpN = wid >> 2;
    const int row0 = warpM * 16, n0 = warpN * 64;
    const int g = tx >> 2, t4 = tx & 3, q = tx >> 3, rl = tx & 7;
    LaneGeom lg = {row0 + (q & 1) * 8 + rl, (q >> 1) * 8, (q & 1) * 8 + rl, (q >> 1) * 8};
    const int lrA = row0 + g, lrB2 = lrA + 8;

    const __half* W0both = g_Wh + 65536;
    const __half* W1h    = g_Wh + 131072;

    if (tid < 256) {
        float ba = __ldg(&b_agg[tid]);
        s_bagg[tid] = ba;
        s_rbh[tid]  = __float2half_rn(fmaxf(ba, 0.f));
        s_bl0[tid]  = __ldg(&b0v_[tid]);
        s_bl1[tid]  = __ldg(&b1v_[tid]);
    }
    if (tid < 64) {
        ssum[tid] = 0.f;
        int x = __ldg(&node_idx[rB + tid]);
        xs[tid] = x;
        oS[tid] = g_owner[x];
    }
    __syncthreads();
    for (int e = tid; e < 64 * DEG; e += 512)
        nboS[e] = g_owner[__ldg(&nbd[xs[e >> 4] * DEG + (e & 15)])];
    __syncthreads();

    const unsigned h1tA = smem_u32(Anm1);
    const unsigned selfA = smem_u32(selfH1), nm2A = smem_u32(nm2);

    // ---- self H1 tile ----
    compute_h1_tile(aggb, fW0, oS, nboS, s_rbh, s_bl0, ssum, selfH1,
                    Anm1, B0, B1, B2, W0both, tid, n0, lg, lrA, lrB2, t4);

    // ---- 16 neighbor tiles: H1 -> agg2 -> group-max into nm2 ----
#pragma unroll 1
    for (int nt = 0; nt < 16; ++nt) {
        if (tid < 64) {
            int il = nt * 4 + (tid >> 4);
            int n = __ldg(&nbd[xs[il] * DEG + (tid & 15)]);
            s_nid[tid] = n;
            oT[tid] = g_owner[n];
        }
        __syncthreads();
        for (int e = tid; e < 64 * DEG; e += 512)
            nboT[e] = g_owner[__ldg(&nbd[s_nid[e >> 4] * DEG + (e & 15)])];
        __syncthreads();

        // H1 of the 64 neighbor nodes -> h1t (reuses Anm1 region)
        compute_h1_tile(aggb, fW0, oT, nboT, s_rbh, s_bl0, ssum,
                        Anm1, Anm1, B0, B1, B2, W0both, tid, n0, lg, lrA, lrB2, t4);

        // agg2 = relu(h1t @ W_agg + b_agg)
        float c[8][4];
#pragma unroll
        for (int j = 0; j < 8; ++j)
#pragma unroll
            for (int k = 0; k < 4; ++k) c[j][k] = 0.f;
        gemm_pipe(c, h1tA, h1tA + 512, LDH, g_Wh + 262144, 8, B0, B1, B2,
                  tid, n0, lg, 0);

        // bias+relu, max over this warpM group's 16 rows (one batch entry)
#pragma unroll
        for (int j = 0; j < 8; ++j) {
            int n = n0 + j * 8 + 2 * t4;
            float bb0 = s_bagg[n], bb1 = s_bagg[n + 1];
            float a0 = fmaxf(fmaxf(c[j][0] + bb0, 0.f), fmaxf(c[j][2] + bb0, 0.f));
            float a1 = fmaxf(fmaxf(c[j][1] + bb1, 0.f), fmaxf(c[j][3] + bb1, 0.f));
#pragma unroll
            for (int mask = 4; mask <= 16; mask <<= 1) {
                a0 = fmaxf(a0, __shfl_xor_sync(0xffffffffu, a0, mask));
                a1 = fmaxf(a1, __shfl_xor_sync(0xffffffffu, a1, mask));
            }
            *(__half2*)&nm2[(nt * 4 + warpM) * LDH + n] = __floats2half2_rn(a0, a1);
        }
        __syncthreads();   // drains agg2 mma readers; protects smem reuse next tile
    }

    // ---- final GEMM: [selfH1 | nm2] @ W1, K=512 ----
    float c[8][4];
#pragma unroll
    for (int j = 0; j < 8; ++j)
#pragma unroll
        for (int k = 0; k < 4; ++k) c[j][k] = 0.f;
    gemm_pipe(c, selfA, nm2A, LDH, W1h, 16, B0, B1, B2, tid, n0, lg, 0);

    // epilogue: bias+relu+normalize (values stay in registers across barrier)
    float invA, invB;
    {
        float ssA = 0.f, ssB = 0.f;
#pragma unroll
        for (int j = 0; j < 8; ++j) {
            int n = n0 + j * 8 + 2 * t4;
            float bb0 = s_bl1[n], bb1 = s_bl1[n + 1];
            c[j][0] = fmaxf(c[j][0] + bb0, 0.f);
            c[j][1] = fmaxf(c[j][1] + bb1, 0.f);
            c[j][2] = fmaxf(c[j][2] + bb0, 0.f);
            c[j][3] = fmaxf(c[j][3] + bb1, 0.f);
            ssA = fmaf(c[j][0], c[j][0], fmaf(c[j][1], c[j][1], ssA));
            ssB = fmaf(c[j][2], c[j][2], fmaf(c[j][3], c[j][3], ssB));
        }
        ssA += __shfl_xor_sync(0xffffffffu, ssA, 1);
        ssA += __shfl_xor_sync(0xffffffffu, ssA, 2);
        ssB += __shfl_xor_sync(0xffffffffu, ssB, 1);
        ssB += __shfl_xor_sync(0xffffffffu, ssB, 2);
        if (t4 == 0) { atomicAdd(&ssum[lrA], ssA); atomicAdd(&ssum[lrB2], ssB); }
        __syncthreads();
        invA = 1.f / fmaxf(sqrtf(ssum[lrA]), EPS);
        invB = 1.f / fmaxf(sqrtf(ssum[lrB2]), EPS);
    }

    // ---- grid barrier: all d_out reads (aggb/fW0) done before overwrite ----
    __syncthreads();
    if (tid == 0) {
        unsigned phase = atomicAdd(&g_barPhase, 0u);
        unsigned t = atomicAdd(&g_barCount, 1u);
        if (t == gridDim.x - 1) {
            g_barCount = 0u;
            __threadfence();
            atomicAdd(&g_barPhase, 1u);
        } else {
            while (atomicAdd(&g_barPhase, 0u) == phase) { }
        }
    }
    __syncthreads();

    // ---- write out ----
#pragma unroll
    for (int j = 0; j < 8; ++j) {
        int n = n0 + j * 8 + 2 * t4;
        *(float2*)&out[(rB + lrA) * 256 + n] =
            make_float2(c[j][0] * invA, c[j][1] * invA);
        *(float2*)&out[(rB + lrB2) * 256 + n] =
            make_float2(c[j][2] * invB, c[j][3] * invB);
    }
}

// ---------------------------------------------------------------------------
// launch: node_idx, feats, nbd, W_agg, b_agg, W_lin, b_lin  -> out [B,256]
// ---------------------------------------------------------------------------
extern "C" void kernel_launch(void* const* d_in, const int* in_sizes, int n_in,
                              void* d_out, int out_size) {
    const int*   node_idx = (const int*)d_in[0];
    const float* feats    = (const float*)d_in[1];
    const int*   nbd      = (const int*)d_in[2];
    const float* W_agg    = (const float*)d_in[3];
    const float* b_agg    = (const float*)d_in[4];
    const float* W_lin    = (const float*)d_in[5];  // [2, 512, 256]
    const float* b_lin    = (const float*)d_in[6];  // [2, 256]

    // d_out: [0, 4.19MB) aggb fp16 | [4.19MB, 8.39MB) fW0 fp16 (exact fit)
    __half* aggb = (__half*)d_out;
    __half* fW0  = (__half*)d_out + BATCH * WIDTH;
    float*  out  = (float*)d_out;                  // overwritten post-barrier

    cudaFuncSetAttribute(pre_gemm_kernel,
                         cudaFuncAttributeMaxDynamicSharedMemorySize, PRE_SMEM);
    cudaFuncSetAttribute(final2_kernel,
                         cudaFuncAttributeMaxDynamicSharedMemorySize, F2_SMEM);

    dim3 gblk(32, 16);
    init_owner_kernel<<<(N_NODES + 255) / 256, 256>>>();
    owner_scatter_kernel<<<(BATCH + 255) / 256, 256>>>(node_idx);
    convert_w_kernel<<<640, 256>>>(W_agg, W_lin);
    pre_gemm_kernel<<<BATCH / 64, gblk, PRE_SMEM>>>(feats, b_agg, aggb, fW0);
    final2_kernel<<<BATCH / 64, gblk, F2_SMEM>>>(
        node_idx, nbd, b_agg, b_lin, b_lin + 256, aggb, fW0, out);
}

// round 15
// speedup vs baseline: 1.2675x; 1.0677x over previous
#include <cuda_runtime.h>
#include <cuda_fp16.h>
#include <math.h>

#define N_NODES 50000
#define DEG     16
#define WIDTH   256
#define BATCH   8192
#define EPS     1e-12f

#define LDB  264    // B staging leading dim (halves): 528B rows, conflict-free
#define LDH  264    // A/H1/nm2 smem leading dim (halves)

// ---- device globals: ~0.85MB total ----
__device__ int      g_owner[N_NODES];          // 200KB
__device__ __half   g_Wh[327680];              // 640KB: W0top|W0bot|W1|Wagg (fp16)
__device__ unsigned g_barCount;
__device__ unsigned g_barPhase;

// ---------------------------------------------------------------------------
// mma helpers
// ---------------------------------------------------------------------------
__device__ __forceinline__ unsigned smem_u32(const void* p) {
    return (unsigned)__cvta_generic_to_shared(p);
}
__device__ __forceinline__ void ldm_x4(unsigned& r0, unsigned& r1, unsigned& r2,
                                       unsigned& r3, unsigned a) {
    asm volatile("ldmatrix.sync.aligned.m8n8.x4.shared.b16 {%0,%1,%2,%3},[%4];"
                 : "=r"(r0), "=r"(r1), "=r"(r2), "=r"(r3) : "r"(a));
}
__device__ __forceinline__ void ldm_x4t(unsigned& r0, unsigned& r1, unsigned& r2,
                                        unsigned& r3, unsigned a) {
    asm volatile("ldmatrix.sync.aligned.m8n8.x4.trans.shared.b16 {%0,%1,%2,%3},[%4];"
                 : "=r"(r0), "=r"(r1), "=r"(r2), "=r"(r3) : "r"(a));
}
__device__ __forceinline__ void mma16816(float* c, unsigned a0, unsigned a1,
                                         unsigned a2, unsigned a3,
                                         unsigned b0, unsigned b1) {
    asm volatile(
        "mma.sync.aligned.m16n8k16.row.col.f32.f16.f16.f32 "
        "{%0,%1,%2,%3},{%4,%5,%6,%7},{%8,%9},{%0,%1,%2,%3};"
        : "+f"(c[0]), "+f"(c[1]), "+f"(c[2]), "+f"(c[3])
        : "r"(a0), "r"(a1), "r"(a2), "r"(a3), "r"(b0), "r"(b1));
}

struct LaneGeom { int aRow, aCol, bRow, bCol; };

__device__ __forceinline__ void mma_chunk(float (*c)[4], unsigned aBase, int lda,
                                          unsigned bBase, int n0, const LaneGeom& lg) {
#pragma unroll
    for (int ks = 0; ks < 2; ++ks) {
        const int k0 = ks * 16;
        unsigned a0, a1, a2, a3;
        ldm_x4(a0, a1, a2, a3,
               aBase + (unsigned)((lg.aRow * lda + k0 + lg.aCol) * 2));
#pragma unroll
        for (int jj = 0; jj < 4; ++jj) {
            unsigned b0, b1, b2, b3;
            ldm_x4t(b0, b1, b2, b3,
                    bBase + (unsigned)(((k0 + lg.bRow) * LDB + n0 + jj * 16 + lg.bCol) * 2));
            mma16816(c[2 * jj],     a0, a1, a2, a3, b0, b1);
            mma16816(c[2 * jj + 1], a0, a1, a2, a3, b2, b3);
        }
    }
}

// async-copy one 32-row fp16 W chunk (16KB) into a B buffer
__device__ __forceinline__ void issue_B(const __half* Wh, int kbase, __half* buf, int tid) {
#pragma unroll
    for (int p = 0; p < 2; ++p) {
        int o = tid + p * 512;
        int kk = o >> 5, seg = o & 31;
        unsigned dst = smem_u32(buf + kk * LDB + seg * 8);
        unsigned long long src =
            (unsigned long long)__cvta_generic_to_global(Wh + (kbase + kk) * 256 + seg * 8);
        asm volatile("cp.async.cg.shared.global [%0],[%1],16;" :: "r"(dst), "l"(src));
    }
    asm volatile("cp.async.commit_group;" ::: "memory");
}

// double-buffered pipelined GEMM over nChunks 32-K chunks (PROVEN R11 version).
__device__ __forceinline__ void gemm_pipe(float (*c)[4], unsigned aLo, unsigned aHi,
                                          int lda, const __half* Wh, int nChunks,
                                          __half* b0, __half* b1, int tid, int n0,
                                          const LaneGeom& lg, bool pre0) {
    if (!pre0) issue_B(Wh, 0, b0, tid);
#pragma unroll 1
    for (int t = 0; t < nChunks; ++t) {
        __half* cur = (t & 1) ? b1 : b0;
        __half* nxt = (t & 1) ? b0 : b1;
        if (t + 1 < nChunks) {
            issue_B(Wh, (t + 1) * 32, nxt, tid);
            asm volatile("cp.async.wait_group 1;" ::: "memory");
        } else {
            asm volatile("cp.async.wait_group 0;" ::: "memory");
        }
        __syncthreads();
        unsigned aB = (t < 8) ? (aLo + (unsigned)(t * 64))
                              : (aHi + (unsigned)((t - 8) * 64));
        mma_chunk(c, aB, lda, smem_u32(cur), n0, lg);
        __syncthreads();
    }
}

// ---------------------------------------------------------------------------
// setup kernels
// ---------------------------------------------------------------------------
__global__ void init_owner_kernel() {
    int i = blockIdx.x * 256 + threadIdx.x;
    if (i < N_NODES) g_owner[i] = -1;
}
__global__ void owner_scatter_kernel(const int* __restrict__ node_idx) {
    int i = blockIdx.x * 256 + threadIdx.x;
    if (i < BATCH) atomicMax(&g_owner[node_idx[i]], i);   // last-wins on dups
}
// g_Wh = [W0top (256x256) | W0bot (256x256) | W1 (512x256) | Wagg (256x256)]
__global__ void convert_w_kernel(const float* __restrict__ W_agg,
                                 const float* __restrict__ W_lin) {
    int i = blockIdx.x * 256 + threadIdx.x;   // half2 index
    if (i < 131072) {
        float2 v = ((const float2*)W_lin)[i];
        ((__half2*)g_Wh)[i] = __floats2half2_rn(v.x, v.y);
    } else if (i < 163840) {
        float2 v = ((const float2*)W_agg)[i - 131072];
        ((__half2*)g_Wh)[i] = __floats2half2_rn(v.x, v.y);
    }
}

// ---------------------------------------------------------------------------
// merged pre GEMM (K=256): stage feats tile once, then
//   aggb = relu(feats @ Wagg + b_agg)   (fp16)
//   fW0  = feats @ W0top                (fp16)
// ---------------------------------------------------------------------------
#define PRE_SMEM (64*LDH*2 + 2*32*LDB*2 + 256*4)   // 68608

__global__ __launch_bounds__(512, 1)
void pre_gemm_kernel(const float* __restrict__ A, const float* __restrict__ bias_agg,
                     __half* __restrict__ aggb, __half* __restrict__ fW0) {
    extern __shared__ char smp[];
    __half* Af  = (__half*)smp;            // [64][264]
    __half* b0  = Af + 64 * LDH;
    __half* b1  = b0 + 32 * LDB;
    float*  s_b = (float*)(b1 + 32 * LDB);

    const int tx = threadIdx.x, wid = threadIdx.y;
    const int tid = wid * 32 + tx;
    const int rowBase = blockIdx.x * 64;
    const int warpM = wid & 3, warpN = wid >> 2;
    const int row0 = warpM * 16, n0 = warpN * 64;
    const int g = tx >> 2, t4 = tx & 3, q = tx >> 3, rl = tx & 7;
    LaneGeom lg = {row0 + (q & 1) * 8 + rl, (q >> 1) * 8, (q & 1) * 8 + rl, (q >> 1) * 8};
    const int lr = tid >> 3, lk4 = tid & 7;

    if (tid < 256) s_b[tid] = __ldg(&bias_agg[tid]);
    issue_B(g_Wh + 262144, 0, b0, tid);    // Wagg chunk 0, overlaps A staging

#pragma unroll
    for (int t = 0; t < 8; ++t) {
        float4 v = *(const float4*)&A[(rowBase + lr) * 256 + t * 32 + lk4 * 4];
        __half2* ad = (__half2*)&Af[lr * LDH + t * 32 + lk4 * 4];
        ad[0] = __floats2half2_rn(v.x, v.y);
        ad[1] = __floats2half2_rn(v.z, v.w);
    }

    const unsigned AfA = smem_u32(Af);
    const int rA = rowBase + row0 + g, rB = rA + 8;

    // ---- GEMM 1: aggb = relu(feats @ Wagg + b_agg) ----
    float c[8][4];
#pragma unroll
    for (int j = 0; j < 8; ++j)
#pragma unroll
        for (int k = 0; k < 4; ++k) c[j][k] = 0.f;
    gemm_pipe(c, AfA, AfA + 512, LDH, g_Wh + 262144, 8, b0, b1, tid, n0, lg, true);
#pragma unroll
    for (int j = 0; j < 8; ++j) {
        int n = n0 + j * 8 + 2 * t4;
        float b0v = s_b[n], b1v = s_b[n + 1];
        *(__half2*)&aggb[rA * 256 + n] =
            __floats2half2_rn(fmaxf(c[j][0] + b0v, 0.f), fmaxf(c[j][1] + b1v, 0.f));
        *(__half2*)&aggb[rB * 256 + n] =
            __floats2half2_rn(fmaxf(c[j][2] + b0v, 0.f), fmaxf(c[j][3] + b1v, 0.f));
    }

    // ---- GEMM 2: fW0 = feats @ W0top ----
#pragma unroll
    for (int j = 0; j < 8; ++j)
#pragma unroll
        for (int k = 0; k < 4; ++k) c[j][k] = 0.f;
    gemm_pipe(c, AfA, AfA + 512, LDH, g_Wh, 8, b0, b1, tid, n0, lg, false);
#pragma unroll
    for (int j = 0; j < 8; ++j) {
        int n = n0 + j * 8 + 2 * t4;
        *(__half2*)&fW0[rA * 256 + n] = __floats2half2_rn(c[j][0], c[j][1]);
        *(__half2*)&fW0[rB * 256 + n] = __floats2half2_rn(c[j][2], c[j][3]);
    }
}

// ---------------------------------------------------------------------------
// H1 tile builder (K=256): vectorized fp16 nm1 gather (uint4 + __hmax2,
// fully unrolled DEG -> MLP=16); accumulator init from fW0[owner]; GEMM vs
// W0bot; bias+relu+normalize. ssum[]==0 on entry; leaves 0.  (exact R11)
// ---------------------------------------------------------------------------
__device__ __forceinline__ void compute_h1_tile(
    const __half* __restrict__ aggb, const __half* __restrict__ fW0,
    const int* __restrict__ oArr, const int* __restrict__ nboArr,
    const __half* __restrict__ s_rbh, const float* __restrict__ s_bl0,
    float* __restrict__ ssum, __half* __restrict__ dstH1,
    __half* __restrict__ Anm1, __half* __restrict__ b0, __half* __restrict__ b1,
    const __half* __restrict__ W0both,
    int tid, int n0, const LaneGeom& lg, int lrA, int lrB2, int t4) {

    const int lr = tid >> 3, lk4 = tid & 7;
    issue_B(W0both, 0, b0, tid);           // overlap W load with gather

    // nm1 gather: 16B loads, fp16 max, direct fp16 store into A tile
    const int* nbo = &nboArr[lr * DEG];
#pragma unroll 1
    for (int t = 0; t < 4; ++t) {
        const int colh = t * 64 + lk4 * 8;         // half offset within row
        uint4 rbv = *(const uint4*)&s_rbh[colh];
        int on0 = nbo[0];
        uint4 w0 = (on0 >= 0) ? __ldg((const uint4*)&aggb[on0 * 256 + colh]) : rbv;
        __half2 m0 = *(__half2*)&w0.x, m1 = *(__half2*)&w0.y;
        __half2 m2 = *(__half2*)&w0.z, m3 = *(__half2*)&w0.w;
#pragma unroll
        for (int d = 1; d < DEG; ++d) {
            int on = nbo[d];
            uint4 w = (on >= 0) ? __ldg((const uint4*)&aggb[on * 256 + colh]) : rbv;
            m0 = __hmax2(m0, *(__half2*)&w.x);
            m1 = __hmax2(m1, *(__half2*)&w.y);
            m2 = __hmax2(m2, *(__half2*)&w.z);
            m3 = __hmax2(m3, *(__half2*)&w.w);
        }
        uint4 mv;
        mv.x = *(unsigned*)&m0; mv.y = *(unsigned*)&m1;
        mv.z = *(unsigned*)&m2; mv.w = *(unsigned*)&m3;
        *(uint4*)&Anm1[lr * LDH + colh] = mv;
    }

    // init accumulator from fW0[owner] (H0 @ W0top contribution)
    float c[8][4];
    {
        const int oA = oArr[lrA], oB = oArr[lrB2];
#pragma unroll
        for (int j = 0; j < 8; ++j) {
            int n = n0 + j * 8 + 2 * t4;
            if (oA >= 0) {
                __half2 v = __ldg((const __half2*)&fW0[oA * 256 + n]);
                c[j][0] = __half2float(v.x); c[j][1] = __half2float(v.y);
            } else { c[j][0] = 0.f; c[j][1] = 0.f; }
            if (oB >= 0) {
                __half2 v = __ldg((const __half2*)&fW0[oB * 256 + n]);
                c[j][2] = __half2float(v.x); c[j][3] = __half2float(v.y);
            } else { c[j][2] = 0.f; c[j][3] = 0.f; }
        }
    }

    unsigned AnA = smem_u32(Anm1);
    gemm_pipe(c, AnA, AnA + 512, LDH, W0both, 8, b0, b1, tid, n0, lg, true);

    // epilogue: bias+relu, cross-warpN row-norm, write fp16 (dstH1 may alias Anm1)
    float ssA = 0.f, ssB = 0.f;
#pragma unroll
    for (int j = 0; j < 8; ++j) {
        int n = n0 + j * 8 + 2 * t4;
        float b0v = s_bl0[n], b1v = s_bl0[n + 1];
        c[j][0] = fmaxf(c[j][0] + b0v, 0.f);
        c[j][1] = fmaxf(c[j][1] + b1v, 0.f);
        c[j][2] = fmaxf(c[j][2] + b0v, 0.f);
        c[j][3] = fmaxf(c[j][3] + b1v, 0.f);
        ssA = fmaf(c[j][0], c[j][0], fmaf(c[j][1], c[j][1], ssA));
        ssB = fmaf(c[j][2], c[j][2], fmaf(c[j][3], c[j][3], ssB));
    }
    ssA += __shfl_xor_sync(0xffffffffu, ssA, 1);
    ssA += __shfl_xor_sync(0xffffffffu, ssA, 2);
    ssB += __shfl_xor_sync(0xffffffffu, ssB, 1);
    ssB += __shfl_xor_sync(0xffffffffu, ssB, 2);
    if (t4 == 0) { atomicAdd(&ssum[lrA], ssA); atomicAdd(&ssum[lrB2], ssB); }
    __syncthreads();
    float invA = 1.f / fmaxf(sqrtf(ssum[lrA]), EPS);
    float invB = 1.f / fmaxf(sqrtf(ssum[lrB2]), EPS);
    __syncthreads();
    if (tid < 64) ssum[tid] = 0.f;
#pragma unroll
    for (int j = 0; j < 8; ++j) {
        int n = n0 + j * 8 + 2 * t4;
        *(__half2*)&dstH1[lrA * LDH + n]  =
            __floats2half2_rn(c[j][0] * invA, c[j][1] * invA);
        *(__half2*)&dstH1[lrB2 * LDH + n] =
            __floats2half2_rn(c[j][2] * invB, c[j][3] * invB);
    }
    __syncthreads();
}

// ---------------------------------------------------------------------------
// final2: one block per 64 batch rows; K=256 H1 tiles; metadata for tile
// nt+1 is prefetched under tile nt's GEMMs (ping-pong sets; publication via
// the GEMMs' internal __syncthreads).
// ---------------------------------------------------------------------------
#define F2_SMEM (3*64*LDH*2 + 2*32*LDB*2 + (256*3+64)*4 + 256*2 + (64+64+128+128+1024+2048)*4)

__global__ __launch_bounds__(512, 1)
void final2_kernel(const int* __restrict__ node_idx, const int* __restrict__ nbd,
                   const float* __restrict__ b_agg, const float* __restrict__ b0v_,
                   const float* __restrict__ b1v_,
                   const __half* __restrict__ aggb, const __half* __restrict__ fW0,
                   float* __restrict__ out) {
    extern __shared__ char smp[];
    __half* Anm1   = (__half*)smp;                 // [64][264]; reused as h1t
    __half* selfH1 = Anm1 + 64 * LDH;              // [64][264]
    __half* nm2    = selfH1 + 64 * LDH;            // [64][264]
    __half* b0     = nm2 + 64 * LDH;               // [32][264]
    __half* b1     = b0 + 32 * LDB;                // [32][264]
    float*  s_bagg = (float*)(b1 + 32 * LDB);      // 256
    float*  s_bl0  = s_bagg + 256;
    float*  s_bl1  = s_bl0 + 256;
    float*  ssum   = s_bl1 + 256;                  // 64
    __half* s_rbh  = (__half*)(ssum + 64);         // 256 halves: relu(b_agg) fp16
    int*    xs     = (int*)(s_rbh + 256);          // 64
    int*    oS     = xs + 64;                      // 64
    int*    s_nid  = oS + 64;                      // [2][64]
    int*    oT     = s_nid + 128;                  // [2][64]
    int*    nboS   = oT + 128;                     // 1024
    int*    nboT   = nboS + 1024;                  // [2][1024]

    const int tx = threadIdx.x, wid = threadIdx.y;
    const int tid = wid * 32 + tx;
    const int rB = blockIdx.x * 64;
    const int warpM = wid & 3, warpN = wid >> 2;
    const int row0 = warpM * 16, n0 = warpN * 64;
    const int g = tx >> 2, t4 = tx & 3, q = tx >> 3, rl = tx & 7;
    LaneGeom lg = {row0 + (q & 1) * 8 + rl, (q >> 1) * 8, (q & 1) * 8 + rl, (q >> 1) * 8};
    const int lrA = row0 + g, lrB2 = lrA + 8;

    const __half* W0both = g_Wh + 65536;
    const __half* W1h    = g_Wh + 131072;

    if (tid < 256) {
        float ba = __ldg(&b_agg[tid]);
        s_bagg[tid] = ba;
        s_rbh[tid]  = __float2half_rn(fmaxf(ba, 0.f));
        s_bl0[tid]  = __ldg(&b0v_[tid]);
        s_bl1[tid]  = __ldg(&b1v_[tid]);
    }
    if (tid < 64) {
        ssum[tid] = 0.f;
        int x = __ldg(&node_idx[rB + tid]);
        xs[tid] = x;
        oS[tid] = g_owner[x];
    }
    __syncthreads();
    for (int e = tid; e < 64 * DEG; e += 512)
        nboS[e] = g_owner[__ldg(&nbd[xs[e >> 4] * DEG + (e & 15)])];
    __syncthreads();

    const unsigned h1tA = smem_u32(Anm1);
    const unsigned selfA = smem_u32(selfH1), nm2A = smem_u32(nm2);

    // round-1 prefetch for neighbor tile 0 (published by self-tile's GEMM syncs)
    if (tid < 64) {
        int n = __ldg(&nbd[xs[tid >> 4] * DEG + (tid & 15)]);   // il = 0*4 + ...
        s_nid[tid] = n;
        oT[tid] = g_owner[n];
    }

    // ---- self H1 tile ----
    compute_h1_tile(aggb, fW0, oS, nboS, s_rbh, s_bl0, ssum, selfH1,
                    Anm1, b0, b1, W0both, tid, n0, lg, lrA, lrB2, t4);

    // round-2 prefetch for tile 0
    for (int e = tid; e < 64 * DEG; e += 512)
        nboT[e] = g_owner[__ldg(&nbd[s_nid[e >> 4] * DEG + (e & 15)])];
    __syncthreads();

    // ---- 16 neighbor tiles: H1 -> agg2 -> group-max into nm2 ----
#pragma unroll 1
    for (int nt = 0; nt < 16; ++nt) {
        const int cur = nt & 1, nxt = cur ^ 1;

        // H1 of the 64 neighbor nodes -> h1t (reuses Anm1 region)
        compute_h1_tile(aggb, fW0, &oT[cur * 64], &nboT[cur * 1024],
                        s_rbh, s_bl0, ssum,
                        Anm1, Anm1, b0, b1, W0both, tid, n0, lg, lrA, lrB2, t4);

        // round-1 prefetch for tile nt+1 (published by agg2 GEMM's syncs)
        if (nt < 15 && tid < 64) {
            int il = (nt + 1) * 4 + (tid >> 4);
            int n = __ldg(&nbd[xs[il] * DEG + (tid & 15)]);
            s_nid[nxt * 64 + tid] = n;
            oT[nxt * 64 + tid] = g_owner[n];
        }

        // agg2 = relu(h1t @ W_agg + b_agg)
        float c[8][4];
#pragma unroll
        for (int j = 0; j < 8; ++j)
#pragma unroll
            for (int k = 0; k < 4; ++k) c[j][k] = 0.f;
        gemm_pipe(c, h1tA, h1tA + 512, LDH, g_Wh + 262144, 8, b0, b1,
                  tid, n0, lg, false);

        // round-2 prefetch for tile nt+1 (published by the tile-end sync)
        if (nt < 15) {
            for (int e = tid; e < 64 * DEG; e += 512)
                nboT[nxt * 1024 + e] =
                    g_owner[__ldg(&nbd[s_nid[nxt * 64 + (e >> 4)] * DEG + (e & 15)])];
        }

        // bias+relu, max over this warpM group's 16 rows (one batch entry)
#pragma unroll
        for (int j = 0; j < 8; ++j) {
            int n = n0 + j * 8 + 2 * t4;
            float bb0 = s_bagg[n], bb1 = s_bagg[n + 1];
            float a0 = fmaxf(fmaxf(c[j][0] + bb0, 0.f), fmaxf(c[j][2] + bb0, 0.f));
            float a1 = fmaxf(fmaxf(c[j][1] + bb1, 0.f), fmaxf(c[j][3] + bb1, 0.f));
#pragma unroll
            for (int mask = 4; mask <= 16; mask <<= 1) {
                a0 = fmaxf(a0, __shfl_xor_sync(0xffffffffu, a0, mask));
                a1 = fmaxf(a1, __shfl_xor_sync(0xffffffffu, a1, mask));
            }
            *(__half2*)&nm2[(nt * 4 + warpM) * LDH + n] = __floats2half2_rn(a0, a1);
        }
        __syncthreads();   // publishes nm2 writes AND round-2 prefetch
    }

    // ---- final GEMM: [selfH1 | nm2] @ W1, K=512 ----
    float c[8][4];
#pragma unroll
    for (int j = 0; j < 8; ++j)
#pragma unroll
        for (int k = 0; k < 4; ++k) c[j][k] = 0.f;
    gemm_pipe(c, selfA, nm2A, LDH, W1h, 16, b0, b1, tid, n0, lg, false);

    // epilogue: bias+relu+normalize (values stay in registers across barrier)
    float invA, invB;
    {
        float ssA = 0.f, ssB = 0.f;
#pragma unroll
        for (int j = 0; j < 8; ++j) {
            int n = n0 + j * 8 + 2 * t4;
            float bb0 = s_bl1[n], bb1 = s_bl1[n + 1];
            c[j][0] = fmaxf(c[j][0] + bb0, 0.f);
            c[j][1] = fmaxf(c[j][1] + bb1, 0.f);
            c[j][2] = fmaxf(c[j][2] + bb0, 0.f);
            c[j][3] = fmaxf(c[j][3] + bb1, 0.f);
            ssA = fmaf(c[j][0], c[j][0], fmaf(c[j][1], c[j][1], ssA));
            ssB = fmaf(c[j][2], c[j][2], fmaf(c[j][3], c[j][3], ssB));
        }
        ssA += __shfl_xor_sync(0xffffffffu, ssA, 1);
        ssA += __shfl_xor_sync(0xffffffffu, ssA, 2);
        ssB += __shfl_xor_sync(0xffffffffu, ssB, 1);
        ssB += __shfl_xor_sync(0xffffffffu, ssB, 2);
        if (t4 == 0) { atomicAdd(&ssum[lrA], ssA); atomicAdd(&ssum[lrB2], ssB); }
        __syncthreads();
        invA = 1.f / fmaxf(sqrtf(ssum[lrA]), EPS);
        invB = 1.f / fmaxf(sqrtf(ssum[lrB2]), EPS);
    }

    // ---- grid barrier: all d_out reads (aggb/fW0) done before overwrite ----
    __syncthreads();
    if (tid == 0) {
        unsigned phase = atomicAdd(&g_barPhase, 0u);
        unsigned t = atomicAdd(&g_barCount, 1u);
        if (t == gridDim.x - 1) {
            g_barCount = 0u;
            __threadfence();
            atomicAdd(&g_barPhase, 1u);
        } else {
            while (atomicAdd(&g_barPhase, 0u) == phase) { }
        }
    }
    __syncthreads();

    // ---- write out ----
#pragma unroll
    for (int j = 0; j < 8; ++j) {
        int n = n0 + j * 8 + 2 * t4;
        *(float2*)&out[(rB + lrA) * 256 + n] =
            make_float2(c[j][0] * invA, c[j][1] * invA);
        *(float2*)&out[(rB + lrB2) * 256 + n] =
            make_float2(c[j][2] * invB, c[j][3] * invB);
    }
}

// ---------------------------------------------------------------------------
// launch: node_idx, feats, nbd, W_agg, b_agg, W_lin, b_lin  -> out [B,256]
// ---------------------------------------------------------------------------
extern "C" void kernel_launch(void* const* d_in, const int* in_sizes, int n_in,
                              void* d_out, int out_size) {
    const int*   node_idx = (const int*)d_in[0];
    const float* feats    = (const float*)d_in[1];
    const int*   nbd      = (const int*)d_in[2];
    const float* W_agg    = (const float*)d_in[3];
    const float* b_agg    = (const float*)d_in[4];
    const float* W_lin    = (const float*)d_in[5];  // [2, 512, 256]
    const float* b_lin    = (const float*)d_in[6];  // [2, 256]

    // d_out: [0, 4.19MB) aggb fp16 | [4.19MB, 8.39MB) fW0 fp16 (exact fit)
    __half* aggb = (__half*)d_out;
    __half* fW0  = (__half*)d_out + BATCH * WIDTH;
    float*  out  = (float*)d_out;                  // overwritten post-barrier

    cudaFuncSetAttribute(pre_gemm_kernel,
                         cudaFuncAttributeMaxDynamicSharedMemorySize, PRE_SMEM);
    cudaFuncSetAttribute(final2_kernel,
                         cudaFuncAttributeMaxDynamicSharedMemorySize, F2_SMEM);

    dim3 gblk(32, 16);
    init_owner_kernel<<<(N_NODES + 255) / 256, 256>>>();
    owner_scatter_kernel<<<(BATCH + 255) / 256, 256>>>(node_idx);
    convert_w_kernel<<<640, 256>>>(W_agg, W_lin);
    pre_gemm_kernel<<<BATCH / 64, gblk, PRE_SMEM>>>(feats, b_agg, aggb, fW0);
    final2_kernel<<<BATCH / 64, gblk, F2_SMEM>>>(
        node_idx, nbd, b_agg, b_lin, b_lin + 256, aggb, fW0, out);
}